// round 1
// baseline (speedup 1.0000x reference)
#include <cuda_runtime.h>
#include <cstdint>

#define NH 32
#define KVH 8
#define HD 128
#define BM 128
#define BN 64
#define NWARP 8
#define NTHREADS 256
#define KPAD 132   // sK/sV row stride in floats (conflict-free B-frag reads)
#define PPAD 68    // sP row stride in floats
#define SMEM_UINTS (2*BN*KPAD + NWARP*16*PPAD)
#define SMEM_BYTES (SMEM_UINTS*4)

__device__ __forceinline__ uint32_t f2tf(float f){
  uint32_t u; asm("cvt.rna.tf32.f32 %0, %1;" : "=r"(u) : "f"(f)); return u;
}

__device__ __forceinline__ void mma8(float c[4], uint32_t a0, uint32_t a1, uint32_t a2, uint32_t a3,
                                     uint32_t b0, uint32_t b1){
  asm volatile(
    "mma.sync.aligned.m16n8k8.row.col.f32.tf32.tf32.f32 "
    "{%0,%1,%2,%3}, {%4,%5,%6,%7}, {%8,%9}, {%0,%1,%2,%3};"
    : "+f"(c[0]), "+f"(c[1]), "+f"(c[2]), "+f"(c[3])
    : "r"(a0), "r"(a1), "r"(a2), "r"(a3), "r"(b0), "r"(b1));
}

__global__ __launch_bounds__(NTHREADS, 1)
void fa_tf32_kernel(const float* __restrict__ q, const float* __restrict__ k,
                    const float* __restrict__ v, float* __restrict__ out)
{
  extern __shared__ uint32_t smem[];
  uint32_t* sK = smem;                 // [BN][KPAD] tf32
  uint32_t* sV = smem + BN*KPAD;       // [BN][KPAD] tf32
  uint32_t* sP = smem + 2*BN*KPAD;     // NWARP x [16][PPAD] tf32

  // reverse qtile order: heaviest CTAs first (load balance across waves)
  const int qtile = (int)(gridDim.x - 1u - blockIdx.x);
  const int head  = blockIdx.y;
  const int kvh   = head >> 2;         // group_size = NH/KVH = 4
  const int q0    = qtile * BM;

  const int tid  = threadIdx.x;
  const int wid  = tid >> 5;
  const int lane = tid & 31;
  const int g = lane >> 2;             // groupID (row selector)
  const int t = lane & 3;              // thread-in-group (col selector)

  // fold 1/sqrt(H) * log2(e) into Q so softmax uses exp2 directly
  const float qscale = 1.4426950408889634f * 0.08838834764831845f;

  const int r0 = q0 + wid*16 + g;      // global q rows this thread owns
  const int r1 = r0 + 8;

  // ---- Q fragments in registers: 16 k-tiles x 4 regs (reused for all kv tiles)
  uint32_t qa[16][4];
  {
    const float* qp0 = q + (size_t)r0 * (NH*HD) + head*HD;
    const float* qp1 = q + (size_t)r1 * (NH*HD) + head*HD;
    #pragma unroll
    for (int kt = 0; kt < 16; kt++){
      int c = kt*8 + t;
      qa[kt][0] = f2tf(qp0[c]   * qscale);
      qa[kt][1] = f2tf(qp1[c]   * qscale);
      qa[kt][2] = f2tf(qp0[c+4] * qscale);
      qa[kt][3] = f2tf(qp1[c+4] * qscale);
    }
  }

  float o[16][4];
  #pragma unroll
  for (int i=0;i<16;i++){ o[i][0]=0.f; o[i][1]=0.f; o[i][2]=0.f; o[i][3]=0.f; }
  float m0=-1e30f, m1=-1e30f, l0=0.f, l1=0.f;

  uint32_t* sPw = sP + wid*(16*PPAD);
  const int ntiles = 2*qtile + 2;      // kv tiles needed (causal)

  for (int it = 0; it < ntiles; it++){
    const int s0 = it * BN;

    __syncthreads();                   // prev-iter smem reads done before overwrite
    // ---- stage K,V tile -> smem as tf32 (coalesced float4 loads)
    #pragma unroll
    for (int i=0;i<8;i++){
      int idx = tid + i*NTHREADS;      // 0..2047 (64 rows x 32 float4)
      int sl  = idx >> 5;
      int h4  = (idx & 31) << 2;
      size_t goff = ((size_t)(s0+sl)*KVH + kvh)*HD + h4;
      float4 kk4 = *(const float4*)(k + goff);
      float4 vv4 = *(const float4*)(v + goff);
      uint32_t* dk = sK + sl*KPAD + h4;
      dk[0]=f2tf(kk4.x); dk[1]=f2tf(kk4.y); dk[2]=f2tf(kk4.z); dk[3]=f2tf(kk4.w);
      uint32_t* dv = sV + sl*KPAD + h4;
      dv[0]=f2tf(vv4.x); dv[1]=f2tf(vv4.y); dv[2]=f2tf(vv4.z); dv[3]=f2tf(vv4.w);
    }
    __syncthreads();

    // tile fully masked for this warp iff s0 > all its rows (alignment guarantees all-or-nothing)
    if (s0 <= q0 + wid*16){
      // ---- S = Q K^T  (16x64 per warp)
      float sc[8][4];
      #pragma unroll
      for (int n=0;n<8;n++){ sc[n][0]=0.f; sc[n][1]=0.f; sc[n][2]=0.f; sc[n][3]=0.f; }
      #pragma unroll
      for (int kt=0; kt<16; kt++){
        #pragma unroll
        for (int n=0;n<8;n++){
          const uint32_t* bp = sK + (n*8+g)*KPAD + kt*8 + t;
          mma8(sc[n], qa[kt][0],qa[kt][1],qa[kt][2],qa[kt][3], bp[0], bp[4]);
        }
      }

      // ---- causal mask (only on diagonal tiles for this warp)
      if (s0 + BN - 1 > q0 + wid*16){
        #pragma unroll
        for (int n=0;n<8;n++){
          int c = s0 + n*8 + 2*t;
          if (c   > r0) sc[n][0] = -1e30f;
          if (c+1 > r0) sc[n][1] = -1e30f;
          if (c   > r1) sc[n][2] = -1e30f;
          if (c+1 > r1) sc[n][3] = -1e30f;
        }
      }

      // ---- online softmax (scores already in log2 units)
      float tm0=-1e30f, tm1=-1e30f;
      #pragma unroll
      for (int n=0;n<8;n++){
        tm0 = fmaxf(tm0, fmaxf(sc[n][0], sc[n][1]));
        tm1 = fmaxf(tm1, fmaxf(sc[n][2], sc[n][3]));
      }
      tm0 = fmaxf(tm0, __shfl_xor_sync(0xffffffffu, tm0, 1));
      tm0 = fmaxf(tm0, __shfl_xor_sync(0xffffffffu, tm0, 2));
      tm1 = fmaxf(tm1, __shfl_xor_sync(0xffffffffu, tm1, 1));
      tm1 = fmaxf(tm1, __shfl_xor_sync(0xffffffffu, tm1, 2));
      float nm0 = fmaxf(m0, tm0), nm1 = fmaxf(m1, tm1);
      float al0 = exp2f(m0 - nm0), al1 = exp2f(m1 - nm1);
      m0 = nm0; m1 = nm1;
      l0 *= al0; l1 *= al1;

      #pragma unroll
      for (int n=0;n<8;n++){
        float p00 = exp2f(sc[n][0]-nm0);
        float p01 = exp2f(sc[n][1]-nm0);
        float p10 = exp2f(sc[n][2]-nm1);
        float p11 = exp2f(sc[n][3]-nm1);
        l0 += p00 + p01; l1 += p10 + p11;
        uint32_t* pr0 = sPw + g*PPAD + n*8 + 2*t;
        pr0[0]=f2tf(p00); pr0[1]=f2tf(p01);
        uint32_t* pr1 = sPw + (g+8)*PPAD + n*8 + 2*t;
        pr1[0]=f2tf(p10); pr1[1]=f2tf(p11);
      }
      #pragma unroll
      for (int n=0;n<16;n++){
        o[n][0]*=al0; o[n][1]*=al0; o[n][2]*=al1; o[n][3]*=al1;
      }
      __syncwarp();   // sP visible warp-wide

      // ---- O += P V  (16x128 per warp)
      #pragma unroll
      for (int kk=0;kk<8;kk++){
        uint32_t pa0 = sPw[ g   *PPAD + kk*8 + t];
        uint32_t pa1 = sPw[(g+8)*PPAD + kk*8 + t];
        uint32_t pa2 = sPw[ g   *PPAD + kk*8 + t + 4];
        uint32_t pa3 = sPw[(g+8)*PPAD + kk*8 + t + 4];
        #pragma unroll
        for (int n=0;n<16;n++){
          uint32_t b0 = sV[(kk*8+t  )*KPAD + n*8 + g];
          uint32_t b1 = sV[(kk*8+t+4)*KPAD + n*8 + g];
          mma8(o[n], pa0,pa1,pa2,pa3, b0,b1);
        }
      }
      // next-iter __syncthreads orders sP reads before rewrites
    }
  }

  // ---- finalize: quad-reduce row sums, normalize, write out
  l0 += __shfl_xor_sync(0xffffffffu, l0, 1);
  l0 += __shfl_xor_sync(0xffffffffu, l0, 2);
  l1 += __shfl_xor_sync(0xffffffffu, l1, 1);
  l1 += __shfl_xor_sync(0xffffffffu, l1, 2);
  float inv0 = 1.0f/l0, inv1 = 1.0f/l1;
  float* op0 = out + (size_t)r0*(NH*HD) + head*HD;
  float* op1 = out + (size_t)r1*(NH*HD) + head*HD;
  #pragma unroll
  for (int n=0;n<16;n++){
    int c = n*8 + 2*t;
    float2 w0 = make_float2(o[n][0]*inv0, o[n][1]*inv0);
    float2 w1 = make_float2(o[n][2]*inv1, o[n][3]*inv1);
    *(float2*)(op0 + c) = w0;
    *(float2*)(op1 + c) = w1;
  }
}

extern "C" void kernel_launch(void* const* d_in, const int* in_sizes, int n_in,
                              void* d_out, int out_size){
  const float* q = (const float*)d_in[0];
  const float* k = (const float*)d_in[1];
  const float* v = (const float*)d_in[2];
  float* out = (float*)d_out;
  int Tq = in_sizes[0] / (NH*HD);     // 2048
  cudaFuncSetAttribute(fa_tf32_kernel, cudaFuncAttributeMaxDynamicSharedMemorySize, SMEM_BYTES);
  dim3 grid(Tq / BM, NH, 1);
  fa_tf32_kernel<<<grid, NTHREADS, SMEM_BYTES>>>(q, k, v, out);
}

// round 2
// speedup vs baseline: 1.0048x; 1.0048x over previous
#include <cuda_runtime.h>
#include <cstdint>

#define NH 32
#define KVH 8
#define HD 128
#define BM 128
#define BN 64
#define NWARP 8
#define NTHREADS 256
#define KPAD 132   // sK/sV row stride in floats (conflict-free B-frag reads)
#define PPAD 68    // sP row stride in floats
#define SMEM_UINTS (2*BN*KPAD + NWARP*16*PPAD)
#define SMEM_BYTES (SMEM_UINTS*4)

__device__ __forceinline__ uint32_t f2tf(float f){
  uint32_t u; asm("cvt.rna.tf32.f32 %0, %1;" : "=r"(u) : "f"(f)); return u;
}

__device__ __forceinline__ void mma8(float c[4], uint32_t a0, uint32_t a1, uint32_t a2, uint32_t a3,
                                     uint32_t b0, uint32_t b1){
  asm volatile(
    "mma.sync.aligned.m16n8k8.row.col.f32.tf32.tf32.f32 "
    "{%0,%1,%2,%3}, {%4,%5,%6,%7}, {%8,%9}, {%0,%1,%2,%3};"
    : "+f"(c[0]), "+f"(c[1]), "+f"(c[2]), "+f"(c[3])
    : "r"(a0), "r"(a1), "r"(a2), "r"(a3), "r"(b0), "r"(b1));
}

__global__ __launch_bounds__(NTHREADS, 1)
void fa_tf32_kernel(const float* __restrict__ q, const float* __restrict__ k,
                    const float* __restrict__ v, float* __restrict__ out)
{
  extern __shared__ uint32_t smem[];
  uint32_t* sK = smem;                 // [BN][KPAD] tf32
  uint32_t* sV = smem + BN*KPAD;       // [BN][KPAD] tf32
  uint32_t* sP = smem + 2*BN*KPAD;     // NWARP x [16][PPAD] tf32

  // reverse qtile order: heaviest CTAs first (load balance across waves)
  const int qtile = (int)(gridDim.x - 1u - blockIdx.x);
  const int head  = blockIdx.y;
  const int kvh   = head >> 2;         // group_size = NH/KVH = 4
  const int q0    = qtile * BM;

  const int tid  = threadIdx.x;
  const int wid  = tid >> 5;
  const int lane = tid & 31;
  const int g = lane >> 2;             // groupID (row selector)
  const int t = lane & 3;              // thread-in-group (col selector)

  // fold 1/sqrt(H) * log2(e) into Q so softmax uses exp2 directly
  const float qscale = 1.4426950408889634f * 0.08838834764831845f;

  const int r0 = q0 + wid*16 + g;      // global q rows this thread owns
  const int r1 = r0 + 8;

  // ---- Q fragments in registers: 16 k-tiles x 4 regs (reused for all kv tiles)
  uint32_t qa[16][4];
  {
    const float* qp0 = q + (size_t)r0 * (NH*HD) + head*HD;
    const float* qp1 = q + (size_t)r1 * (NH*HD) + head*HD;
    #pragma unroll
    for (int kt = 0; kt < 16; kt++){
      int c = kt*8 + t;
      qa[kt][0] = f2tf(qp0[c]   * qscale);
      qa[kt][1] = f2tf(qp1[c]   * qscale);
      qa[kt][2] = f2tf(qp0[c+4] * qscale);
      qa[kt][3] = f2tf(qp1[c+4] * qscale);
    }
  }

  float o[16][4];
  #pragma unroll
  for (int i=0;i<16;i++){ o[i][0]=0.f; o[i][1]=0.f; o[i][2]=0.f; o[i][3]=0.f; }
  float m0=-1e30f, m1=-1e30f, l0=0.f, l1=0.f;

  uint32_t* sPw = sP + wid*(16*PPAD);
  const int ntiles = 2*qtile + 2;      // kv tiles needed (causal)

  for (int it = 0; it < ntiles; it++){
    const int s0 = it * BN;

    __syncthreads();                   // prev-iter smem reads done before overwrite
    // ---- stage K,V tile -> smem as tf32 (coalesced float4 loads)
    #pragma unroll
    for (int i=0;i<8;i++){
      int idx = tid + i*NTHREADS;      // 0..2047 (64 rows x 32 float4)
      int sl  = idx >> 5;
      int h4  = (idx & 31) << 2;
      size_t goff = ((size_t)(s0+sl)*KVH + kvh)*HD + h4;
      float4 kk4 = *(const float4*)(k + goff);
      float4 vv4 = *(const float4*)(v + goff);
      uint32_t* dk = sK + sl*KPAD + h4;
      dk[0]=f2tf(kk4.x); dk[1]=f2tf(kk4.y); dk[2]=f2tf(kk4.z); dk[3]=f2tf(kk4.w);
      uint32_t* dv = sV + sl*KPAD + h4;
      dv[0]=f2tf(vv4.x); dv[1]=f2tf(vv4.y); dv[2]=f2tf(vv4.z); dv[3]=f2tf(vv4.w);
    }
    __syncthreads();

    // tile fully masked for this warp iff s0 > all its rows (alignment guarantees all-or-nothing)
    if (s0 <= q0 + wid*16){
      // ---- S = Q K^T  (16x64 per warp)
      float sc[8][4];
      #pragma unroll
      for (int n=0;n<8;n++){ sc[n][0]=0.f; sc[n][1]=0.f; sc[n][2]=0.f; sc[n][3]=0.f; }
      #pragma unroll
      for (int kt=0; kt<16; kt++){
        #pragma unroll
        for (int n=0;n<8;n++){
          const uint32_t* bp = sK + (n*8+g)*KPAD + kt*8 + t;
          mma8(sc[n], qa[kt][0],qa[kt][1],qa[kt][2],qa[kt][3], bp[0], bp[4]);
        }
      }

      // ---- causal mask (only on diagonal tiles for this warp)
      if (s0 + BN - 1 > q0 + wid*16){
        #pragma unroll
        for (int n=0;n<8;n++){
          int c = s0 + n*8 + 2*t;
          if (c   > r0) sc[n][0] = -1e30f;
          if (c+1 > r0) sc[n][1] = -1e30f;
          if (c   > r1) sc[n][2] = -1e30f;
          if (c+1 > r1) sc[n][3] = -1e30f;
        }
      }

      // ---- online softmax (scores already in log2 units)
      float tm0=-1e30f, tm1=-1e30f;
      #pragma unroll
      for (int n=0;n<8;n++){
        tm0 = fmaxf(tm0, fmaxf(sc[n][0], sc[n][1]));
        tm1 = fmaxf(tm1, fmaxf(sc[n][2], sc[n][3]));
      }
      tm0 = fmaxf(tm0, __shfl_xor_sync(0xffffffffu, tm0, 1));
      tm0 = fmaxf(tm0, __shfl_xor_sync(0xffffffffu, tm0, 2));
      tm1 = fmaxf(tm1, __shfl_xor_sync(0xffffffffu, tm1, 1));
      tm1 = fmaxf(tm1, __shfl_xor_sync(0xffffffffu, tm1, 2));
      float nm0 = fmaxf(m0, tm0), nm1 = fmaxf(m1, tm1);
      float al0 = exp2f(m0 - nm0), al1 = exp2f(m1 - nm1);
      m0 = nm0; m1 = nm1;
      l0 *= al0; l1 *= al1;

      #pragma unroll
      for (int n=0;n<8;n++){
        float p00 = exp2f(sc[n][0]-nm0);
        float p01 = exp2f(sc[n][1]-nm0);
        float p10 = exp2f(sc[n][2]-nm1);
        float p11 = exp2f(sc[n][3]-nm1);
        l0 += p00 + p01; l1 += p10 + p11;
        uint32_t* pr0 = sPw + g*PPAD + n*8 + 2*t;
        pr0[0]=f2tf(p00); pr0[1]=f2tf(p01);
        uint32_t* pr1 = sPw + (g+8)*PPAD + n*8 + 2*t;
        pr1[0]=f2tf(p10); pr1[1]=f2tf(p11);
      }
      #pragma unroll
      for (int n=0;n<16;n++){
        o[n][0]*=al0; o[n][1]*=al0; o[n][2]*=al1; o[n][3]*=al1;
      }
      __syncwarp();   // sP visible warp-wide

      // ---- O += P V  (16x128 per warp)
      #pragma unroll
      for (int kk=0;kk<8;kk++){
        uint32_t pa0 = sPw[ g   *PPAD + kk*8 + t];
        uint32_t pa1 = sPw[(g+8)*PPAD + kk*8 + t];
        uint32_t pa2 = sPw[ g   *PPAD + kk*8 + t + 4];
        uint32_t pa3 = sPw[(g+8)*PPAD + kk*8 + t + 4];
        #pragma unroll
        for (int n=0;n<16;n++){
          uint32_t b0 = sV[(kk*8+t  )*KPAD + n*8 + g];
          uint32_t b1 = sV[(kk*8+t+4)*KPAD + n*8 + g];
          mma8(o[n], pa0,pa1,pa2,pa3, b0,b1);
        }
      }
      // next-iter __syncthreads orders sP reads before rewrites
    }
  }

  // ---- finalize: quad-reduce row sums, normalize, write out
  l0 += __shfl_xor_sync(0xffffffffu, l0, 1);
  l0 += __shfl_xor_sync(0xffffffffu, l0, 2);
  l1 += __shfl_xor_sync(0xffffffffu, l1, 1);
  l1 += __shfl_xor_sync(0xffffffffu, l1, 2);
  float inv0 = 1.0f/l0, inv1 = 1.0f/l1;
  float* op0 = out + (size_t)r0*(NH*HD) + head*HD;
  float* op1 = out + (size_t)r1*(NH*HD) + head*HD;
  #pragma unroll
  for (int n=0;n<16;n++){
    int c = n*8 + 2*t;
    float2 w0 = make_float2(o[n][0]*inv0, o[n][1]*inv0);
    float2 w1 = make_float2(o[n][2]*inv1, o[n][3]*inv1);
    *(float2*)(op0 + c) = w0;
    *(float2*)(op1 + c) = w1;
  }
}

extern "C" void kernel_launch(void* const* d_in, const int* in_sizes, int n_in,
                              void* d_out, int out_size){
  const float* q = (const float*)d_in[0];
  const float* k = (const float*)d_in[1];
  const float* v = (const float*)d_in[2];
  float* out = (float*)d_out;
  int Tq = in_sizes[0] / (NH*HD);     // 2048
  cudaFuncSetAttribute(fa_tf32_kernel, cudaFuncAttributeMaxDynamicSharedMemorySize, SMEM_BYTES);
  dim3 grid(Tq / BM, NH, 1);
  fa_tf32_kernel<<<grid, NTHREADS, SMEM_BYTES>>>(q, k, v, out);
}